// round 6
// baseline (speedup 1.0000x reference)
#include <cuda_runtime.h>

// Problem constants
#define Bq   8
#define Np   4096
#define Cc   256
#define Sq   512
#define NSk  64
#define NROWS_L (Bq*Sq*NSk)   /* 262144 */
#define NROWS_G (Bq*Np)       /* 32768  */

// ---------------- device scratch (static, allocation-free) ----------------
__device__ int   d_idx[NROWS_L];                    // ball query indices
__device__ float d_Wc[256*256];                     // [w10[:,3:]; w20[:,3:]] row-major [o][c]
__device__ float d_Wx1[128*3];                      // w10[:,0:3]
__device__ float d_Wx2[128*3];                      // w20[:,0:3]
__device__ float d_F0 [(size_t)NROWS_G*128];        // dense local layer0 feature part [b*N+j][o]
__device__ float d_zgA[(size_t)NROWS_G*128];        // global branch ping
__device__ float d_zgB[(size_t)NROWS_G*128];        // global branch pong
__device__ float d_zlA[(size_t)NROWS_L*128];        // local branch ping
__device__ float d_zlB[(size_t)NROWS_L*128];        // local branch pong
__device__ float d_stats[6][2][128];                // per-stage {sum, sumsq}
__device__ float d_ab[6][2][128];                   // per-stage {scale a, shift b}
__device__ float d_gpart[Bq*32*128];                // global maxpool partials

// Buffer id -> device pointer, resolved IN DEVICE CODE (host must never pass
// __device__ symbols as kernel args: on GB300 ATS the host shadow address is
// silently dereferenced as host memory -> zeros, the Round-3/4 bug).
__device__ __forceinline__ float* bufptr(int w) {
    switch (w) {
        case 0:  return d_zlA;
        case 1:  return d_zlB;
        case 2:  return d_zgA;
        default: return d_zgB;
    }
}

// ---------------- tiny helpers ----------------
__global__ void k_zero_stats() {
    int i = threadIdx.x;
    if (i < 128)
        for (int s = 0; s < 6; s++)
            for (int h = 0; h < 2; h++)
                d_stats[s][h][i] = 0.f;
}

__global__ void k_prep(const float* __restrict__ w10, const float* __restrict__ w20) {
    int i = blockIdx.x * blockDim.x + threadIdx.x;   // 0 .. 65535
    if (i < 256 * 256) {
        int o = i >> 8, c = i & 255;
        d_Wc[i] = (o < 128) ? w10[o * 259 + 3 + c] : w20[(o - 128) * 259 + 3 + c];
    }
    if (i < 128 * 3) {
        int o = i / 3, dd = i % 3;
        d_Wx1[i] = w10[o * 259 + dd];
        d_Wx2[i] = w20[o * 259 + dd];
    }
}

// ---------------- ball query + new_xyz ----------------
// grid (S/8, B), block 256 (8 warps, one warp per query)
__global__ void k_ballquery(const float* __restrict__ xyz,
                            const int*   __restrict__ inds,
                            float*       __restrict__ out_xyz) {
    __shared__ float sx[Np];
    __shared__ float sy[Np];
    __shared__ float sz[Np];
    int b = blockIdx.y;
    int t = threadIdx.x;
    const float* xb = xyz + (size_t)b * Np * 3;
    for (int i = t; i < Np; i += 256) {
        sx[i] = xb[i * 3 + 0];
        sy[i] = xb[i * 3 + 1];
        sz[i] = xb[i * 3 + 2];
    }
    __syncthreads();

    int w = t >> 5, lane = t & 31;
    int s = blockIdx.x * 8 + w;
    int q = inds[b * Sq + s];
    float qx = sx[q], qy = sy[q], qz = sz[q];
    if (lane == 0) out_xyz[(b * Sq + s) * 3 + 0] = qx;
    if (lane == 1) out_xyz[(b * Sq + s) * 3 + 1] = qy;
    if (lane == 2) out_xyz[(b * Sq + s) * 3 + 2] = qz;

    int* dst = d_idx + ((b * Sq + s) << 6);
    const float R2 = (float)(0.3 * 0.3);
    int count = 0;
    int first = 0;
    for (int base = 0; base < Np; base += 32) {
        int j = base + lane;
        float dx = __fsub_rn(qx, sx[j]);
        float dy = __fsub_rn(qy, sy[j]);
        float dz = __fsub_rn(qz, sz[j]);
        float d2 = __fadd_rn(__fadd_rn(__fmul_rn(dx, dx), __fmul_rn(dy, dy)),
                             __fmul_rn(dz, dz));
        bool p = d2 < R2;
        unsigned m = __ballot_sync(0xffffffffu, p);
        if (count == 0 && m) first = base + __ffs(m) - 1;
        int pos = count + __popc(m & ((1u << lane) - 1u));
        if (p && pos < NSk) dst[pos] = j;
        count += __popc(m);
        if (count >= NSk) break;
    }
    for (int i = count + lane; i < NSk; i += 32) dst[i] = first;
}

// ---------------- dense layer0 GEMM (features -> F0 and z0_global) ----------------
// grid (N/64, 4, B), block 256. M=4096(j) N=256(o) K=256(c).
__global__ __launch_bounds__(256) void k_l0dense(const float* __restrict__ feat,
                                                 const float* __restrict__ xyz) {
    __shared__ float As[32][68];   // [c][j]
    __shared__ float Bs[32][68];   // [c][o]
    int b = blockIdx.z;
    int jB = blockIdx.x * 64, oB = blockIdx.y * 64;
    int t = threadIdx.x, ty = t >> 4, tx = t & 15;
    const float* fb = feat + (size_t)b * Cc * Np;
    float acc[4][4] = {};
    for (int k0 = 0; k0 < 256; k0 += 32) {
        #pragma unroll
        for (int i = 0; i < 8; i++) {
            int e = t + i * 256;
            As[e >> 6][e & 63] = fb[(size_t)(k0 + (e >> 6)) * Np + jB + (e & 63)];
        }
        #pragma unroll
        for (int i = 0; i < 8; i++) {
            int e = t + i * 256;
            Bs[e & 31][e >> 5] = d_Wc[(oB + (e >> 5)) * 256 + k0 + (e & 31)];
        }
        __syncthreads();
        #pragma unroll
        for (int kk = 0; kk < 32; kk++) {
            float a[4], bb[4];
            #pragma unroll
            for (int r = 0; r < 4; r++) a[r] = As[kk][ty * 4 + r];
            #pragma unroll
            for (int c2 = 0; c2 < 4; c2++) bb[c2] = Bs[kk][tx * 4 + c2];
            #pragma unroll
            for (int r = 0; r < 4; r++)
                #pragma unroll
                for (int c2 = 0; c2 < 4; c2++)
                    acc[r][c2] = fmaf(a[r], bb[c2], acc[r][c2]);
        }
        __syncthreads();
    }
    int oG = oB + tx * 4;
    if (oG < 128) {
        #pragma unroll
        for (int r = 0; r < 4; r++) {
            int j = jB + ty * 4 + r;
            float* dst = d_F0 + ((size_t)(b * Np + j)) * 128 + oG;
            dst[0] = acc[r][0]; dst[1] = acc[r][1]; dst[2] = acc[r][2]; dst[3] = acc[r][3];
        }
    } else {
        #pragma unroll
        for (int r = 0; r < 4; r++) {
            int j = jB + ty * 4 + r;
            const float* px = xyz + ((size_t)(b * Np + j)) * 3;
            float x0 = px[0], x1 = px[1], x2 = px[2];
            float* dst = d_zgA + ((size_t)(b * Np + j)) * 128 + (oG - 128);
            #pragma unroll
            for (int c2 = 0; c2 < 4; c2++) {
                int o = oG - 128 + c2;
                dst[c2] = acc[r][c2] + d_Wx2[o * 3 + 0] * x0
                                     + d_Wx2[o * 3 + 1] * x1
                                     + d_Wx2[o * 3 + 2] * x2;
            }
        }
    }
}

// ---------------- local layer0 assemble: gather F0 + xyz term ----------------
// grid NROWS_L/2, block 256 (2 rows/block, 1 channel/thread)
__global__ void k_assemble(const float* __restrict__ xyz,
                           const float* __restrict__ nxyz) {
    int row = blockIdx.x * 2 + (threadIdx.x >> 7);
    int o   = threadIdx.x & 127;
    int b = row >> 15;
    int s = (row >> 6) & 511;
    int j = d_idx[row];
    const float* nx = nxyz + ((size_t)(b * Sq + s)) * 3;
    const float* px = xyz  + ((size_t)(b * Np + j)) * 3;
    float gx = __fdiv_rn(__fsub_rn(px[0], nx[0]), 0.3f);
    float gy = __fdiv_rn(__fsub_rn(px[1], nx[1]), 0.3f);
    float gz = __fdiv_rn(__fsub_rn(px[2], nx[2]), 0.3f);
    float v = d_F0[((size_t)(b * Np + j)) * 128 + o]
            + d_Wx1[o * 3 + 0] * gx
            + d_Wx1[o * 3 + 1] * gy
            + d_Wx1[o * 3 + 2] * gz;
    d_zlA[(size_t)row * 128 + o] = v;
}

// ---------------- per-channel sum/sumsq reduction ----------------
__global__ void k_stats(int bufid, int rows, int stage) {
    const float* __restrict__ buf = bufptr(bufid);
    int o    = threadIdx.x & 127;
    int half = threadIdx.x >> 7;
    float s = 0.f, s2 = 0.f;
    for (int r = blockIdx.x * 2 + half; r < rows; r += gridDim.x * 2) {
        float v = buf[(size_t)r * 128 + o];
        s += v; s2 += v * v;
    }
    __shared__ float sh[2][128], sh2[2][128];
    sh[half][o] = s; sh2[half][o] = s2;
    __syncthreads();
    if (half == 0) {
        atomicAdd(&d_stats[stage][0][o], s + sh[1][o]);
        atomicAdd(&d_stats[stage][1][o], s2 + sh2[1][o]);
    }
}

__global__ void k_finalize(int stage, float invCnt,
                           const float* __restrict__ g,
                           const float* __restrict__ be) {
    int o = threadIdx.x;   // 128
    float mu  = d_stats[stage][0][o] * invCnt;
    float var = d_stats[stage][1][o] * invCnt - mu * mu;
    float a = g[o] / sqrtf(var + 1e-5f);
    d_ab[stage][0][o] = a;
    d_ab[stage][1][o] = be[o] - mu * a;
}

// ---------------- 128x128 layer GEMM with fused BN+ReLU on input ----------------
// grid rows/128, block 256. out[row][o] = sum_c W[o][c]*relu(a[c]*in[row][c]+b[c])
__global__ __launch_bounds__(256) void k_gemm128(int inid, int outid,
                                                 const float* __restrict__ W,
                                                 int stage) {
    const float* __restrict__ in = bufptr(inid);
    float* __restrict__ outb     = bufptr(outid);
    __shared__ float Xs[16][132];   // [c][row]
    __shared__ float Ws[16][132];   // [c][o]
    __shared__ float sa[128], sb2[128];
    int t = threadIdx.x;
    if (t < 128) { sa[t] = d_ab[stage][0][t]; sb2[t] = d_ab[stage][1][t]; }
    __syncthreads();
    size_t rowBase = (size_t)blockIdx.x * 128;
    int ty = t >> 4, tx = t & 15;
    float acc[8][8] = {};
    for (int k0 = 0; k0 < 128; k0 += 16) {
        #pragma unroll
        for (int i = 0; i < 8; i++) {
            int e = t + i * 256;
            int r = e >> 4, c = e & 15;
            float v = in[(rowBase + r) * 128 + k0 + c];
            Xs[c][r] = fmaxf(fmaf(sa[k0 + c], v, sb2[k0 + c]), 0.f);
            Ws[c][r] = W[r * 128 + k0 + c];   // r doubles as output channel o here
        }
        __syncthreads();
        #pragma unroll
        for (int kk = 0; kk < 16; kk++) {
            float av[8], bv[8];
            float4 t0 = *(const float4*)&Xs[kk][ty * 8];
            float4 t1 = *(const float4*)&Xs[kk][ty * 8 + 4];
            av[0]=t0.x; av[1]=t0.y; av[2]=t0.z; av[3]=t0.w;
            av[4]=t1.x; av[5]=t1.y; av[6]=t1.z; av[7]=t1.w;
            float4 u0 = *(const float4*)&Ws[kk][tx * 8];
            float4 u1 = *(const float4*)&Ws[kk][tx * 8 + 4];
            bv[0]=u0.x; bv[1]=u0.y; bv[2]=u0.z; bv[3]=u0.w;
            bv[4]=u1.x; bv[5]=u1.y; bv[6]=u1.z; bv[7]=u1.w;
            #pragma unroll
            for (int r = 0; r < 8; r++)
                #pragma unroll
                for (int c = 0; c < 8; c++)
                    acc[r][c] = fmaf(av[r], bv[c], acc[r][c]);
        }
        __syncthreads();
    }
    #pragma unroll
    for (int r = 0; r < 8; r++) {
        float* dst = outb + (rowBase + ty * 8 + r) * 128 + tx * 8;
        *(float4*)(dst)     = make_float4(acc[r][0], acc[r][1], acc[r][2], acc[r][3]);
        *(float4*)(dst + 4) = make_float4(acc[r][4], acc[r][5], acc[r][6], acc[r][7]);
    }
}

// ---------------- max pools + output writes ----------------
__global__ void k_maxlocal(float* __restrict__ outF) {
    int bs = blockIdx.x;            // b*512 + s
    int o  = threadIdx.x;           // 128
    float a = d_ab[2][0][o], bb = d_ab[2][1][o];
    const float* base = d_zlA + (size_t)bs * NSk * 128 + o;
    float m = 0.f;                  // relu folded: max(0, max_k(a*z+b))
    #pragma unroll 4
    for (int k = 0; k < NSk; k++) m = fmaxf(m, fmaf(a, base[k * 128], bb));
    int b = bs >> 9, s = bs & 511;
    outF[((size_t)b * 256 + o) * 512 + s] = m;
}

// global pool stage 1: grid (32, B), block 128 — each block reduces 128 points
__global__ void k_gmax1() {
    int b = blockIdx.y, sl = blockIdx.x, o = threadIdx.x;
    float a = d_ab[5][0][o], bb = d_ab[5][1][o];
    const float* base = d_zgA + ((size_t)b * Np + sl * 128) * 128 + o;
    float m = 0.f;
    #pragma unroll 4
    for (int k = 0; k < 128; k++) m = fmaxf(m, fmaf(a, base[k * 128], bb));
    d_gpart[(b * 32 + sl) * 128 + o] = m;
}

// global pool stage 2: grid B, block 256 — combine + coalesced broadcast write
__global__ void k_gmax2(float* __restrict__ outF) {
    __shared__ float sm[128];
    int b = blockIdx.x, t = threadIdx.x;
    if (t < 128) {
        float m = 0.f;
        for (int sl = 0; sl < 32; sl++) m = fmaxf(m, d_gpart[(b * 32 + sl) * 128 + t]);
        sm[t] = m;
    }
    __syncthreads();
    for (int i = t; i < 128 * 512; i += 256) {
        int o = i >> 9, s = i & 511;
        outF[((size_t)b * 256 + 128 + o) * 512 + s] = sm[o];
    }
}

// ---------------- launch ----------------
extern "C" void kernel_launch(void* const* d_in, const int* in_sizes, int n_in,
                              void* d_out, int out_size) {
    (void)in_sizes; (void)n_in; (void)out_size;
    const float* xyz  = (const float*)d_in[0];
    const float* feat = (const float*)d_in[1];
    const int*   inds = (const int*)  d_in[2];
    const float* w10  = (const float*)d_in[3];
    const float* g10  = (const float*)d_in[4];
    const float* be10 = (const float*)d_in[5];
    const float* w11  = (const float*)d_in[6];
    const float* g11  = (const float*)d_in[7];
    const float* be11 = (const float*)d_in[8];
    const float* w12  = (const float*)d_in[9];
    const float* g12  = (const float*)d_in[10];
    const float* be12 = (const float*)d_in[11];
    const float* w20  = (const float*)d_in[12];
    const float* g20  = (const float*)d_in[13];
    const float* be20 = (const float*)d_in[14];
    const float* w21  = (const float*)d_in[15];
    const float* g21  = (const float*)d_in[16];
    const float* be21 = (const float*)d_in[17];
    const float* w22  = (const float*)d_in[18];
    const float* g22  = (const float*)d_in[19];
    const float* be22 = (const float*)d_in[20];

    float* out      = (float*)d_out;
    float* out_xyz  = out;                       // (B,S,3)
    float* out_feat = out + (size_t)Bq * Sq * 3; // (B,256,S)

    const float invL = 1.0f / (float)NROWS_L;
    const float invG = 1.0f / (float)NROWS_G;

    // buffer ids: 0=zlA 1=zlB 2=zgA 3=zgB
    k_zero_stats<<<1, 256>>>();
    k_prep<<<256, 256>>>(w10, w20);
    k_ballquery<<<dim3(Sq / 8, Bq), 256>>>(xyz, inds, out_xyz);

    // layer 0 (dense feature GEMM + global-branch xyz term)
    k_l0dense<<<dim3(Np / 64, 4, Bq), 256>>>(feat, xyz);

    // global branch layer0 stats
    k_stats<<<256, 256>>>(2, NROWS_G, 3);
    k_finalize<<<1, 128>>>(3, invG, g20, be20);

    // local branch assemble (needs new_xyz + idx)
    k_assemble<<<NROWS_L / 2, 256>>>(xyz, out_xyz);
    k_stats<<<2048, 256>>>(0, NROWS_L, 0);
    k_finalize<<<1, 128>>>(0, invL, g10, be10);

    // local layers 1 & 2
    k_gemm128<<<NROWS_L / 128, 256>>>(0, 1, w11, 0);
    k_stats<<<2048, 256>>>(1, NROWS_L, 1);
    k_finalize<<<1, 128>>>(1, invL, g11, be11);

    k_gemm128<<<NROWS_L / 128, 256>>>(1, 0, w12, 1);
    k_stats<<<2048, 256>>>(0, NROWS_L, 2);
    k_finalize<<<1, 128>>>(2, invL, g12, be12);

    k_maxlocal<<<Bq * Sq, 128>>>(out_feat);

    // global layers 1 & 2
    k_gemm128<<<NROWS_G / 128, 256>>>(2, 3, w21, 3);
    k_stats<<<256, 256>>>(3, NROWS_G, 4);
    k_finalize<<<1, 128>>>(4, invG, g21, be21);

    k_gemm128<<<NROWS_G / 128, 256>>>(3, 2, w22, 4);
    k_stats<<<256, 256>>>(2, NROWS_G, 5);
    k_finalize<<<1, 128>>>(5, invG, g22, be22);

    k_gmax1<<<dim3(32, Bq), 128>>>();
    k_gmax2<<<Bq, 256>>>(out_feat);
}

// round 11
// speedup vs baseline: 1.6723x; 1.6723x over previous
#include <cuda_runtime.h>

// Problem constants
#define Bq   8
#define Np   4096
#define Cc   256
#define Sq   512
#define NSk  64
#define NROWS_L (Bq*Sq*NSk)   /* 262144 */
#define NROWS_G (Bq*Np)       /* 32768  */

typedef unsigned long long u64;

// ---------------- f32x2 helpers ----------------
__device__ __forceinline__ void ffma2(u64& d, u64 a, u64 b) {
    asm("fma.rn.f32x2 %0, %1, %2, %0;" : "+l"(d) : "l"(a), "l"(b));
}
__device__ __forceinline__ u64 dup2(float x) {
    u64 r; unsigned xi = __float_as_uint(x);
    asm("mov.b64 %0, {%1, %1};" : "=l"(r) : "r"(xi));
    return r;
}
__device__ __forceinline__ float2 up2(u64 v) {
    float2 f;
    asm("mov.b64 {%0, %1}, %2;" : "=f"(f.x), "=f"(f.y) : "l"(v));
    return f;
}

// ---------------- device scratch (static, allocation-free) ----------------
__device__ int   d_idx[NROWS_L];
__device__ float d_Wc[256*256];                     // [w10[:,3:]; w20[:,3:]] [o][c]
__device__ float d_Wx1[128*3];
__device__ float d_Wx2[128*3];
__device__ float d_F0 [(size_t)NROWS_G*128];
__device__ float d_zgA[(size_t)NROWS_G*128];
__device__ float d_zgB[(size_t)NROWS_G*128];
__device__ float d_zlA[(size_t)NROWS_L*128];
__device__ float d_zlB[(size_t)NROWS_L*128];
__device__ float d_stats[6][2][128];
__device__ float d_ab[6][2][128];
__device__ float d_gpart[Bq*32*128];

// device-side buffer resolution (NEVER pass __device__ symbols from host; see R5 bug)
__device__ __forceinline__ float* bufptr(int w) {
    switch (w) {
        case 0:  return d_zlA;
        case 1:  return d_zlB;
        case 2:  return d_zgA;
        default: return d_zgB;
    }
}

// ---------------- tiny helpers ----------------
__global__ void k_zero_stats() {
    int i = threadIdx.x;
    if (i < 128)
        for (int s = 0; s < 6; s++)
            for (int h = 0; h < 2; h++)
                d_stats[s][h][i] = 0.f;
}

__global__ void k_prep(const float* __restrict__ w10, const float* __restrict__ w20) {
    int i = blockIdx.x * blockDim.x + threadIdx.x;
    if (i < 256 * 256) {
        int o = i >> 8, c = i & 255;
        d_Wc[i] = (o < 128) ? w10[o * 259 + 3 + c] : w20[(o - 128) * 259 + 3 + c];
    }
    if (i < 128 * 3) {
        int o = i / 3, dd = i % 3;
        d_Wx1[i] = w10[o * 259 + dd];
        d_Wx2[i] = w20[o * 259 + dd];
    }
}

// ---------------- ball query + new_xyz ----------------
__global__ void k_ballquery(const float* __restrict__ xyz,
                            const int*   __restrict__ inds,
                            float*       __restrict__ out_xyz) {
    __shared__ float sx[Np], sy[Np], sz[Np];
    int b = blockIdx.y;
    int t = threadIdx.x;
    const float* xb = xyz + (size_t)b * Np * 3;
    for (int i = t; i < Np; i += 256) {
        sx[i] = xb[i * 3 + 0];
        sy[i] = xb[i * 3 + 1];
        sz[i] = xb[i * 3 + 2];
    }
    __syncthreads();

    int w = t >> 5, lane = t & 31;
    int s = blockIdx.x * 8 + w;
    int q = inds[b * Sq + s];
    float qx = sx[q], qy = sy[q], qz = sz[q];
    if (lane == 0) out_xyz[(b * Sq + s) * 3 + 0] = qx;
    if (lane == 1) out_xyz[(b * Sq + s) * 3 + 1] = qy;
    if (lane == 2) out_xyz[(b * Sq + s) * 3 + 2] = qz;

    int* dst = d_idx + ((b * Sq + s) << 6);
    const float R2 = (float)(0.3 * 0.3);
    int count = 0, first = 0;
    for (int base = 0; base < Np; base += 32) {
        int j = base + lane;
        float dx = __fsub_rn(qx, sx[j]);
        float dy = __fsub_rn(qy, sy[j]);
        float dz = __fsub_rn(qz, sz[j]);
        float d2 = __fadd_rn(__fadd_rn(__fmul_rn(dx, dx), __fmul_rn(dy, dy)),
                             __fmul_rn(dz, dz));
        bool p = d2 < R2;
        unsigned m = __ballot_sync(0xffffffffu, p);
        if (count == 0 && m) first = base + __ffs(m) - 1;
        int pos = count + __popc(m & ((1u << lane) - 1u));
        if (p && pos < NSk) dst[pos] = j;
        count += __popc(m);
        if (count >= NSk) break;
    }
    for (int i = count + lane; i < NSk; i += 32) dst[i] = first;
}

// ---------------- dense layer0 GEMM (FFMA2, 128x128 tile, K=256) ----------------
// grid (256, 2), block 256. blockIdx.y=0 -> F0 (local feat part), =1 -> zgA (+xyz, +stats stage3)
__global__ __launch_bounds__(256, 2) void k_l0dense(const float* __restrict__ feat,
                                                    const float* __restrict__ xyz) {
    __shared__ float Xs[32][132];   // [c][j]
    __shared__ float Ws[32][132];   // [c][o]
    __shared__ float bsum[128], bsq[128];
    int t = threadIdx.x;
    int oB = blockIdx.y;
    int rowBase = blockIdx.x * 128;          // global row = b*Np + j
    int b  = rowBase >> 12;
    int jb = rowBase & (Np - 1);
    if (t < 128) { bsum[t] = 0.f; bsq[t] = 0.f; }

    int ty = t >> 4, tx = t & 15;
    u64 acc[8][4] = {};
    const float* fb = feat + (size_t)b * Cc * Np + jb;

    for (int k0 = 0; k0 < 256; k0 += 32) {
        __syncthreads();
        #pragma unroll
        for (int i = 0; i < 16; i++) {
            int e = i * 256 + t;
            int c = e >> 7, j = e & 127;
            Xs[c][j] = fb[(size_t)(k0 + c) * Np + j];
        }
        #pragma unroll
        for (int i = 0; i < 16; i++) {
            int e = i * 256 + t;
            int o = e >> 5, c = e & 31;
            Ws[c][o] = d_Wc[(oB * 128 + o) * 256 + k0 + c];
        }
        __syncthreads();
        #pragma unroll 8
        for (int kk = 0; kk < 32; kk++) {
            ulonglong2 b01 = *(const ulonglong2*)&Ws[kk][tx * 8];
            ulonglong2 b23 = *(const ulonglong2*)&Ws[kk][tx * 8 + 4];
            u64 bv[4] = { b01.x, b01.y, b23.x, b23.y };
            uint4 a0 = *(const uint4*)&Xs[kk][ty * 8];
            uint4 a1 = *(const uint4*)&Xs[kk][ty * 8 + 4];
            float av[8] = { __uint_as_float(a0.x), __uint_as_float(a0.y),
                            __uint_as_float(a0.z), __uint_as_float(a0.w),
                            __uint_as_float(a1.x), __uint_as_float(a1.y),
                            __uint_as_float(a1.z), __uint_as_float(a1.w) };
            #pragma unroll
            for (int r = 0; r < 8; r++) {
                u64 ad = dup2(av[r]);
                #pragma unroll
                for (int c2 = 0; c2 < 4; c2++) ffma2(acc[r][c2], ad, bv[c2]);
            }
        }
    }

    if (oB == 0) {
        #pragma unroll
        for (int r = 0; r < 8; r++) {
            float2 p0 = up2(acc[r][0]), p1 = up2(acc[r][1]);
            float2 p2 = up2(acc[r][2]), p3 = up2(acc[r][3]);
            float* dst = d_F0 + ((size_t)(rowBase + ty * 8 + r)) * 128 + tx * 8;
            *(float4*)(dst)     = make_float4(p0.x, p0.y, p1.x, p1.y);
            *(float4*)(dst + 4) = make_float4(p2.x, p2.y, p3.x, p3.y);
        }
    } else {
        float wx[8][3];
        #pragma unroll
        for (int c = 0; c < 8; c++) {
            int o = tx * 8 + c;
            wx[c][0] = d_Wx2[o * 3 + 0];
            wx[c][1] = d_Wx2[o * 3 + 1];
            wx[c][2] = d_Wx2[o * 3 + 2];
        }
        float cs[8] = {}, cq[8] = {};
        #pragma unroll
        for (int r = 0; r < 8; r++) {
            int row = rowBase + ty * 8 + r;
            const float* px = xyz + (size_t)row * 3;
            float x0 = px[0], x1 = px[1], x2 = px[2];
            float v[8];
            float2 p0 = up2(acc[r][0]), p1 = up2(acc[r][1]);
            float2 p2 = up2(acc[r][2]), p3 = up2(acc[r][3]);
            v[0]=p0.x; v[1]=p0.y; v[2]=p1.x; v[3]=p1.y;
            v[4]=p2.x; v[5]=p2.y; v[6]=p3.x; v[7]=p3.y;
            #pragma unroll
            for (int c = 0; c < 8; c++) {
                v[c] += wx[c][0]*x0 + wx[c][1]*x1 + wx[c][2]*x2;
                cs[c] += v[c]; cq[c] += v[c]*v[c];
            }
            float* dst = d_zgA + (size_t)row * 128 + tx * 8;
            *(float4*)(dst)     = make_float4(v[0], v[1], v[2], v[3]);
            *(float4*)(dst + 4) = make_float4(v[4], v[5], v[6], v[7]);
        }
        #pragma unroll
        for (int c = 0; c < 8; c++) {
            atomicAdd(&bsum[tx * 8 + c], cs[c]);
            atomicAdd(&bsq [tx * 8 + c], cq[c]);
        }
        __syncthreads();
        if (t < 128) {
            atomicAdd(&d_stats[3][0][t], bsum[t]);
            atomicAdd(&d_stats[3][1][t], bsq[t]);
        }
    }
}

// ---------------- local layer0 assemble + fused stage0 stats ----------------
// grid 2048, block 128: 128 rows per block, one channel per thread
__global__ void k_assemble(const float* __restrict__ xyz,
                           const float* __restrict__ nxyz) {
    __shared__ float sgx[128], sgy[128], sgz[128];
    __shared__ int   sj[128];
    int o = threadIdx.x;
    int row0 = blockIdx.x * 128;
    // phase A: per-row geometry, one row per thread
    {
        int row = row0 + o;
        int b = row >> 15;
        int s = (row >> 6) & 511;
        int j = d_idx[row];
        const float* nx = nxyz + ((size_t)(b * Sq + s)) * 3;
        const float* px = xyz  + ((size_t)(b * Np + j)) * 3;
        sgx[o] = __fmul_rn(__fsub_rn(px[0], nx[0]), (1.0f/0.3f));
        sgy[o] = __fmul_rn(__fsub_rn(px[1], nx[1]), (1.0f/0.3f));
        sgz[o] = __fmul_rn(__fsub_rn(px[2], nx[2]), (1.0f/0.3f));
        sj[o]  = (b * Np) + j;
    }
    __syncthreads();
    float w0 = d_Wx1[o * 3 + 0], w1 = d_Wx1[o * 3 + 1], w2 = d_Wx1[o * 3 + 2];
    float s1 = 0.f, s2 = 0.f;
    #pragma unroll 4
    for (int rr = 0; rr < 128; rr++) {
        float v = d_F0[(size_t)sj[rr] * 128 + o]
                + w0 * sgx[rr] + w1 * sgy[rr] + w2 * sgz[rr];
        d_zlA[(size_t)(row0 + rr) * 128 + o] = v;
        s1 += v; s2 += v * v;
    }
    atomicAdd(&d_stats[0][0][o], s1);
    atomicAdd(&d_stats[0][1][o], s2);
}

__global__ void k_finalize(int stage, float invCnt,
                           const float* __restrict__ g,
                           const float* __restrict__ be) {
    int o = threadIdx.x;
    float mu  = d_stats[stage][0][o] * invCnt;
    float var = d_stats[stage][1][o] * invCnt - mu * mu;
    float a = g[o] / sqrtf(var + 1e-5f);
    d_ab[stage][0][o] = a;
    d_ab[stage][1][o] = be[o] - mu * a;
}

// ---------------- 128x128 layer GEMM (FFMA2) + fused BN/ReLU in, stats out ----
// grid rows/128, block 256.
__global__ __launch_bounds__(256, 2) void k_gemm128(int inid, int outid,
                                                    const float* __restrict__ W,
                                                    int stageIn, int stageOut) {
    const float* __restrict__ in = bufptr(inid);
    float* __restrict__ outb     = bufptr(outid);
    __shared__ float Xs[128][33];   // [row][c-within-tile]
    __shared__ float Ws[32][132];   // [c][o]
    __shared__ float sa[128], sb[128];
    __shared__ float bsum[128], bsq[128];
    int t = threadIdx.x;
    if (t < 128) {
        sa[t] = d_ab[stageIn][0][t];
        sb[t] = d_ab[stageIn][1][t];
        bsum[t] = 0.f; bsq[t] = 0.f;
    }
    size_t rowBase = (size_t)blockIdx.x * 128;
    int ty = t >> 4, tx = t & 15;
    u64 acc[8][4] = {};

    for (int k0 = 0; k0 < 128; k0 += 32) {
        __syncthreads();
        #pragma unroll
        for (int i = 0; i < 16; i++) {
            int e = i * 256 + t;
            int r = e >> 5, c = e & 31;
            float v = in[(rowBase + r) * 128 + k0 + c];
            Xs[r][c] = fmaxf(fmaf(sa[k0 + c], v, sb[k0 + c]), 0.f);
        }
        #pragma unroll
        for (int i = 0; i < 16; i++) {
            int e = i * 256 + t;
            int o = e >> 5, c = e & 31;
            Ws[c][o] = W[o * 128 + k0 + c];
        }
        __syncthreads();
        #pragma unroll 8
        for (int kk = 0; kk < 32; kk++) {
            ulonglong2 b01 = *(const ulonglong2*)&Ws[kk][tx * 8];
            ulonglong2 b23 = *(const ulonglong2*)&Ws[kk][tx * 8 + 4];
            u64 bv[4] = { b01.x, b01.y, b23.x, b23.y };
            #pragma unroll
            for (int r = 0; r < 8; r++) {
                u64 ad = dup2(Xs[ty * 8 + r][kk]);
                #pragma unroll
                for (int c2 = 0; c2 < 4; c2++) ffma2(acc[r][c2], ad, bv[c2]);
            }
        }
    }

    float cs[8] = {}, cq[8] = {};
    #pragma unroll
    for (int r = 0; r < 8; r++) {
        float v[8];
        float2 p0 = up2(acc[r][0]), p1 = up2(acc[r][1]);
        float2 p2 = up2(acc[r][2]), p3 = up2(acc[r][3]);
        v[0]=p0.x; v[1]=p0.y; v[2]=p1.x; v[3]=p1.y;
        v[4]=p2.x; v[5]=p2.y; v[6]=p3.x; v[7]=p3.y;
        #pragma unroll
        for (int c = 0; c < 8; c++) { cs[c] += v[c]; cq[c] += v[c]*v[c]; }
        float* dst = outb + (rowBase + ty * 8 + r) * 128 + tx * 8;
        *(float4*)(dst)     = make_float4(v[0], v[1], v[2], v[3]);
        *(float4*)(dst + 4) = make_float4(v[4], v[5], v[6], v[7]);
    }
    #pragma unroll
    for (int c = 0; c < 8; c++) {
        atomicAdd(&bsum[tx * 8 + c], cs[c]);
        atomicAdd(&bsq [tx * 8 + c], cq[c]);
    }
    __syncthreads();
    if (t < 128) {
        atomicAdd(&d_stats[stageOut][0][t], bsum[t]);
        atomicAdd(&d_stats[stageOut][1][t], bsq[t]);
    }
}

// ---------------- max pools + output writes ----------------
__global__ void k_maxlocal(float* __restrict__ outF) {
    int bs = blockIdx.x;
    int o  = threadIdx.x;
    float a = d_ab[2][0][o], bb = d_ab[2][1][o];
    const float* base = d_zlA + (size_t)bs * NSk * 128 + o;
    float m = 0.f;
    #pragma unroll 4
    for (int k = 0; k < NSk; k++) m = fmaxf(m, fmaf(a, base[k * 128], bb));
    int b = bs >> 9, s = bs & 511;
    outF[((size_t)b * 256 + o) * 512 + s] = m;
}

__global__ void k_gmax1() {
    int b = blockIdx.y, sl = blockIdx.x, o = threadIdx.x;
    float a = d_ab[5][0][o], bb = d_ab[5][1][o];
    const float* base = d_zgA + ((size_t)b * Np + sl * 128) * 128 + o;
    float m = 0.f;
    #pragma unroll 4
    for (int k = 0; k < 128; k++) m = fmaxf(m, fmaf(a, base[k * 128], bb));
    d_gpart[(b * 32 + sl) * 128 + o] = m;
}

__global__ void k_gmax2(float* __restrict__ outF) {
    __shared__ float sm[128];
    int b = blockIdx.x, t = threadIdx.x;
    if (t < 128) {
        float m = 0.f;
        for (int sl = 0; sl < 32; sl++) m = fmaxf(m, d_gpart[(b * 32 + sl) * 128 + t]);
        sm[t] = m;
    }
    __syncthreads();
    for (int i = t; i < 128 * 512; i += 256) {
        int o = i >> 9, s = i & 511;
        outF[((size_t)b * 256 + 128 + o) * 512 + s] = sm[o];
    }
}

// ---------------- launch ----------------
extern "C" void kernel_launch(void* const* d_in, const int* in_sizes, int n_in,
                              void* d_out, int out_size) {
    (void)in_sizes; (void)n_in; (void)out_size;
    const float* xyz  = (const float*)d_in[0];
    const float* feat = (const float*)d_in[1];
    const int*   inds = (const int*)  d_in[2];
    const float* w10  = (const float*)d_in[3];
    const float* g10  = (const float*)d_in[4];
    const float* be10 = (const float*)d_in[5];
    const float* w11  = (const float*)d_in[6];
    const float* g11  = (const float*)d_in[7];
    const float* be11 = (const float*)d_in[8];
    const float* w12  = (const float*)d_in[9];
    const float* g12  = (const float*)d_in[10];
    const float* be12 = (const float*)d_in[11];
    const float* w20  = (const float*)d_in[12];
    const float* g20  = (const float*)d_in[13];
    const float* be20 = (const float*)d_in[14];
    const float* w21  = (const float*)d_in[15];
    const float* g21  = (const float*)d_in[16];
    const float* be21 = (const float*)d_in[17];
    const float* w22  = (const float*)d_in[18];
    const float* g22  = (const float*)d_in[19];
    const float* be22 = (const float*)d_in[20];

    float* out      = (float*)d_out;
    float* out_xyz  = out;                       // (B,S,3)
    float* out_feat = out + (size_t)Bq * Sq * 3; // (B,256,S)

    const float invL = 1.0f / (float)NROWS_L;
    const float invG = 1.0f / (float)NROWS_G;

    k_zero_stats<<<1, 128>>>();
    k_prep<<<256, 256>>>(w10, w20);
    k_ballquery<<<dim3(Sq / 8, Bq), 256>>>(xyz, inds, out_xyz);

    // layer 0: dense feature GEMM (F0 + global z0 with fused stage3 stats)
    k_l0dense<<<dim3(256, 2), 256>>>(feat, xyz);
    k_finalize<<<1, 128>>>(3, invG, g20, be20);

    // local assemble (fused stage0 stats)
    k_assemble<<<2048, 128>>>(xyz, out_xyz);
    k_finalize<<<1, 128>>>(0, invL, g10, be10);

    // local layers 1 & 2 (fused stats)
    k_gemm128<<<NROWS_L / 128, 256>>>(0, 1, w11, 0, 1);
    k_finalize<<<1, 128>>>(1, invL, g11, be11);
    k_gemm128<<<NROWS_L / 128, 256>>>(1, 0, w12, 1, 2);
    k_finalize<<<1, 128>>>(2, invL, g12, be12);

    k_maxlocal<<<Bq * Sq, 128>>>(out_feat);

    // global layers 1 & 2 (fused stats)
    k_gemm128<<<NROWS_G / 128, 256>>>(2, 3, w21, 3, 4);
    k_finalize<<<1, 128>>>(4, invG, g21, be21);
    k_gemm128<<<NROWS_G / 128, 256>>>(3, 2, w22, 4, 5);
    k_finalize<<<1, 128>>>(5, invG, g22, be22);

    k_gmax1<<<dim3(32, Bq), 128>>>();
    k_gmax2<<<Bq, 256>>>(out_feat);
}

// round 14
// speedup vs baseline: 1.8176x; 1.0869x over previous
#include <cuda_runtime.h>

// Problem constants
#define Bq   8
#define Np   4096
#define Cc   256
#define Sq   512
#define NSk  64
#define NROWS_L (Bq*Sq*NSk)   /* 262144 */
#define NROWS_G (Bq*Np)       /* 32768  */

typedef unsigned long long u64;

// ---------------- f32x2 / async helpers ----------------
__device__ __forceinline__ void ffma2(u64& d, u64 a, u64 b) {
    asm("fma.rn.f32x2 %0, %1, %2, %0;" : "+l"(d) : "l"(a), "l"(b));
}
__device__ __forceinline__ u64 dup2(float x) {
    u64 r; unsigned xi = __float_as_uint(x);
    asm("mov.b64 %0, {%1, %1};" : "=l"(r) : "r"(xi));
    return r;
}
__device__ __forceinline__ float2 up2(u64 v) {
    float2 f;
    asm("mov.b64 {%0, %1}, %2;" : "=f"(f.x), "=f"(f.y) : "l"(v));
    return f;
}
__device__ __forceinline__ void cpa16(float* dst, const float* src) {
    unsigned d = (unsigned)__cvta_generic_to_shared(dst);
    asm volatile("cp.async.cg.shared.global [%0], [%1], 16;" :: "r"(d), "l"(src));
}
#define CP_COMMIT() asm volatile("cp.async.commit_group;")
#define CP_WAIT0()  asm volatile("cp.async.wait_group 0;")

// ---------------- device scratch (static, allocation-free) ----------------
__device__ int   d_idx[NROWS_L];
__device__ float d_WcT[256*256];                    // [c][o]  (o<128: w10 feat part, else w20)
__device__ float d_WTl[4*128*128];                  // transposed w11,w12,w21,w22  [l][c][o]
__device__ float d_Wx1[128*3];
__device__ float d_Wx2[128*3];
__device__ float d_F0 [(size_t)NROWS_G*128];
__device__ float d_zgA[(size_t)NROWS_G*128];
__device__ float d_zgB[(size_t)NROWS_G*128];
__device__ float d_zlA[(size_t)NROWS_L*128];
__device__ float d_zlB[(size_t)NROWS_L*128];
__device__ float d_stats[6][2][128];
__device__ float d_ab[6][2][128];
__device__ float d_gpart[Bq*32*128];

// device-side buffer resolution (NEVER pass __device__ symbols from host; R5 bug)
__device__ __forceinline__ float* bufptr(int w) {
    switch (w) {
        case 0:  return d_zlA;
        case 1:  return d_zlB;
        case 2:  return d_zgA;
        default: return d_zgB;
    }
}

// ---------------- tiny helpers ----------------
__global__ void k_zero_stats() {
    int i = threadIdx.x;
    if (i < 128)
        for (int s = 0; s < 6; s++)
            for (int h = 0; h < 2; h++)
                d_stats[s][h][i] = 0.f;
}

__global__ void k_prep(const float* __restrict__ w10, const float* __restrict__ w20) {
    int i = blockIdx.x * blockDim.x + threadIdx.x;   // 0..65535
    if (i < 256 * 256) {
        int c = i >> 8, o = i & 255;                 // WcT[c][o]
        d_WcT[i] = (o < 128) ? w10[o * 259 + 3 + c] : w20[(o - 128) * 259 + 3 + c];
    }
    if (i < 128 * 3) {
        int o = i / 3, dd = i % 3;
        d_Wx1[i] = w10[o * 259 + dd];
        d_Wx2[i] = w20[o * 259 + dd];
    }
}

__global__ void k_prep2(const float* __restrict__ w11, const float* __restrict__ w12,
                        const float* __restrict__ w21, const float* __restrict__ w22) {
    int i = blockIdx.x * blockDim.x + threadIdx.x;   // 0..65535
    int l = i >> 14, rem = i & 16383;
    int c = rem >> 7, o = rem & 127;
    const float* w = (l == 0) ? w11 : (l == 1) ? w12 : (l == 2) ? w21 : w22;
    d_WTl[i] = w[o * 128 + c];
}

// ---------------- ball query + new_xyz ----------------
__global__ void k_ballquery(const float* __restrict__ xyz,
                            const int*   __restrict__ inds,
                            float*       __restrict__ out_xyz) {
    __shared__ float sx[Np], sy[Np], sz[Np];
    int b = blockIdx.y;
    int t = threadIdx.x;
    const float* xb = xyz + (size_t)b * Np * 3;
    for (int i = t; i < Np; i += 256) {
        sx[i] = xb[i * 3 + 0];
        sy[i] = xb[i * 3 + 1];
        sz[i] = xb[i * 3 + 2];
    }
    __syncthreads();

    int w = t >> 5, lane = t & 31;
    int s = blockIdx.x * 8 + w;
    int q = inds[b * Sq + s];
    float qx = sx[q], qy = sy[q], qz = sz[q];
    if (lane == 0) out_xyz[(b * Sq + s) * 3 + 0] = qx;
    if (lane == 1) out_xyz[(b * Sq + s) * 3 + 1] = qy;
    if (lane == 2) out_xyz[(b * Sq + s) * 3 + 2] = qz;

    int* dst = d_idx + ((b * Sq + s) << 6);
    const float R2 = (float)(0.3 * 0.3);
    int count = 0, first = 0;
    for (int base = 0; base < Np; base += 32) {
        int j = base + lane;
        float dx = __fsub_rn(qx, sx[j]);
        float dy = __fsub_rn(qy, sy[j]);
        float dz = __fsub_rn(qz, sz[j]);
        float d2 = __fadd_rn(__fadd_rn(__fmul_rn(dx, dx), __fmul_rn(dy, dy)),
                             __fmul_rn(dz, dz));
        bool p = d2 < R2;
        unsigned m = __ballot_sync(0xffffffffu, p);
        if (count == 0 && m) first = base + __ffs(m) - 1;
        int pos = count + __popc(m & ((1u << lane) - 1u));
        if (p && pos < NSk) dst[pos] = j;
        count += __popc(m);
        if (count >= NSk) break;
    }
    for (int i = count + lane; i < NSk; i += 32) dst[i] = first;
}

// ---------------- dense layer0 GEMM (FFMA2 + cp.async double buffer) ----------
// grid (256, 2), block 256. K=256 in 8 chunks of 32. X already [c][j] in gmem.
// dyn smem: Xc[2][32*132] | Ws[2][32*132]  = 67584 B
__global__ __launch_bounds__(256, 2) void k_l0dense(const float* __restrict__ feat,
                                                    const float* __restrict__ xyz) {
    extern __shared__ float sm[];
    float* Xc = sm;                 // 2 * 4224
    float* Ws = sm + 2 * 4224;      // 2 * 4224
    __shared__ float bsum[128], bsq[128];
    int t = threadIdx.x;
    int oB = blockIdx.y;
    int rowBase = blockIdx.x * 128;          // global row = b*Np + j
    int b  = rowBase >> 12;
    int jb = rowBase & (Np - 1);
    if (t < 128) { bsum[t] = 0.f; bsq[t] = 0.f; }

    int ty = t >> 4, tx = t & 15;
    const float* fb = feat + (size_t)b * Cc * Np + jb;
    const float* Wg = d_WcT + oB * 128;      // row c: [c*256 + oB*128 .. +128)

    // chunk issue: 4 X copies + 4 W copies per thread
    auto issue = [&](int n) {
        float* xd = Xc + (n & 1) * 4224;
        float* wd = Ws + (n & 1) * 4224;
        #pragma unroll
        for (int q = 0; q < 4; q++) {
            int e = q * 256 + t;
            int c = e >> 5, seg = (e & 31) << 2;
            cpa16(xd + c * 132 + seg, fb + (size_t)(n * 32 + c) * Np + seg);
        }
        #pragma unroll
        for (int q = 0; q < 4; q++) {
            int e = q * 256 + t;
            int c = e >> 5, seg = (e & 31) << 2;
            cpa16(wd + c * 132 + seg, Wg + (n * 32 + c) * 256 + seg);
        }
        CP_COMMIT();
    };

    u64 acc[8][4] = {};
    issue(0);
    for (int i = 0; i < 8; i++) {
        CP_WAIT0();
        __syncthreads();
        if (i + 1 < 8) issue(i + 1);
        const float* Xb = Xc + (i & 1) * 4224;
        const float* Wb = Ws + (i & 1) * 4224;
        #pragma unroll 8
        for (int kk = 0; kk < 32; kk++) {
            ulonglong2 b01 = *(const ulonglong2*)(Wb + kk * 132 + tx * 8);
            ulonglong2 b23 = *(const ulonglong2*)(Wb + kk * 132 + tx * 8 + 4);
            u64 bv[4] = { b01.x, b01.y, b23.x, b23.y };
            float4 a0 = *(const float4*)(Xb + kk * 132 + ty * 8);
            float4 a1 = *(const float4*)(Xb + kk * 132 + ty * 8 + 4);
            float av[8] = { a0.x, a0.y, a0.z, a0.w, a1.x, a1.y, a1.z, a1.w };
            #pragma unroll
            for (int r = 0; r < 8; r++) {
                u64 ad = dup2(av[r]);
                #pragma unroll
                for (int c2 = 0; c2 < 4; c2++) ffma2(acc[r][c2], ad, bv[c2]);
            }
        }
        __syncthreads();
    }

    if (oB == 0) {
        #pragma unroll
        for (int r = 0; r < 8; r++) {
            float2 p0 = up2(acc[r][0]), p1 = up2(acc[r][1]);
            float2 p2 = up2(acc[r][2]), p3 = up2(acc[r][3]);
            float* dst = d_F0 + ((size_t)(rowBase + ty * 8 + r)) * 128 + tx * 8;
            *(float4*)(dst)     = make_float4(p0.x, p0.y, p1.x, p1.y);
            *(float4*)(dst + 4) = make_float4(p2.x, p2.y, p3.x, p3.y);
        }
    } else {
        float wx[8][3];
        #pragma unroll
        for (int c = 0; c < 8; c++) {
            int o = tx * 8 + c;
            wx[c][0] = d_Wx2[o * 3 + 0];
            wx[c][1] = d_Wx2[o * 3 + 1];
            wx[c][2] = d_Wx2[o * 3 + 2];
        }
        float cs[8] = {}, cq[8] = {};
        #pragma unroll
        for (int r = 0; r < 8; r++) {
            int row = rowBase + ty * 8 + r;
            const float* px = xyz + (size_t)row * 3;
            float x0 = px[0], x1 = px[1], x2 = px[2];
            float v[8];
            float2 p0 = up2(acc[r][0]), p1 = up2(acc[r][1]);
            float2 p2 = up2(acc[r][2]), p3 = up2(acc[r][3]);
            v[0]=p0.x; v[1]=p0.y; v[2]=p1.x; v[3]=p1.y;
            v[4]=p2.x; v[5]=p2.y; v[6]=p3.x; v[7]=p3.y;
            #pragma unroll
            for (int c = 0; c < 8; c++) {
                v[c] += wx[c][0]*x0 + wx[c][1]*x1 + wx[c][2]*x2;
                cs[c] += v[c]; cq[c] += v[c]*v[c];
            }
            float* dst = d_zgA + (size_t)row * 128 + tx * 8;
            *(float4*)(dst)     = make_float4(v[0], v[1], v[2], v[3]);
            *(float4*)(dst + 4) = make_float4(v[4], v[5], v[6], v[7]);
        }
        #pragma unroll
        for (int c = 0; c < 8; c++) {
            atomicAdd(&bsum[tx * 8 + c], cs[c]);
            atomicAdd(&bsq [tx * 8 + c], cq[c]);
        }
        __syncthreads();
        if (t < 128) {
            atomicAdd(&d_stats[3][0][t], bsum[t]);
            atomicAdd(&d_stats[3][1][t], bsq[t]);
        }
    }
}

// ---------------- local layer0 assemble + fused stage0 stats ----------------
__global__ void k_assemble(const float* __restrict__ xyz,
                           const float* __restrict__ nxyz) {
    __shared__ float sgx[128], sgy[128], sgz[128];
    __shared__ int   sj[128];
    int o = threadIdx.x;
    int row0 = blockIdx.x * 128;
    {
        int row = row0 + o;
        int b = row >> 15;
        int s = (row >> 6) & 511;
        int j = d_idx[row];
        const float* nx = nxyz + ((size_t)(b * Sq + s)) * 3;
        const float* px = xyz  + ((size_t)(b * Np + j)) * 3;
        sgx[o] = __fmul_rn(__fsub_rn(px[0], nx[0]), (1.0f/0.3f));
        sgy[o] = __fmul_rn(__fsub_rn(px[1], nx[1]), (1.0f/0.3f));
        sgz[o] = __fmul_rn(__fsub_rn(px[2], nx[2]), (1.0f/0.3f));
        sj[o]  = (b * Np) + j;
    }
    __syncthreads();
    float w0 = d_Wx1[o * 3 + 0], w1 = d_Wx1[o * 3 + 1], w2 = d_Wx1[o * 3 + 2];
    float s1 = 0.f, s2 = 0.f;
    #pragma unroll 4
    for (int rr = 0; rr < 128; rr++) {
        float v = d_F0[(size_t)sj[rr] * 128 + o]
                + w0 * sgx[rr] + w1 * sgy[rr] + w2 * sgz[rr];
        d_zlA[(size_t)(row0 + rr) * 128 + o] = v;
        s1 += v; s2 += v * v;
    }
    atomicAdd(&d_stats[0][0][o], s1);
    atomicAdd(&d_stats[0][1][o], s2);
}

__global__ void k_finalize(int stage, float invCnt,
                           const float* __restrict__ g,
                           const float* __restrict__ be) {
    int o = threadIdx.x;
    float mu  = d_stats[stage][0][o] * invCnt;
    float var = d_stats[stage][1][o] * invCnt - mu * mu;
    float a = g[o] / sqrtf(var + 1e-5f);
    d_ab[stage][0][o] = a;
    d_ab[stage][1][o] = be[o] - mu * a;
}

// ---------------- 128x128 layer GEMM (FFMA2 + cp.async + transform) --------
// dyn smem: stX[2][128*32] | Xc[32*132] | Ws[2][32*132]  = 83456 B
__global__ __launch_bounds__(256, 2) void k_gemm128(int inid, int outid, int wl,
                                                    int stageIn, int stageOut) {
    extern __shared__ float sm[];
    float* stX = sm;                      // 2 * 4096
    float* Xc  = sm + 8192;               // 4224
    float* Ws  = sm + 8192 + 4224;        // 2 * 4224
    __shared__ float sa[128], sb[128];
    __shared__ float bsum[128], bsq[128];
    const float* __restrict__ in = bufptr(inid);
    float* __restrict__ outb     = bufptr(outid);
    const float* WT = d_WTl + wl * 16384;
    int t = threadIdx.x;
    if (t < 128) {
        sa[t] = d_ab[stageIn][0][t];
        sb[t] = d_ab[stageIn][1][t];
        bsum[t] = 0.f; bsq[t] = 0.f;
    }
    size_t rowBase = (size_t)blockIdx.x * 128;
    const float* inB = in + rowBase * 128;
    int ty = t >> 4, tx = t & 15;

    auto issue = [&](int n) {
        float* xd = stX + (n & 1) * 4096;
        float* wd = Ws  + (n & 1) * 4224;
        #pragma unroll
        for (int q = 0; q < 4; q++) {
            int e = q * 256 + t;
            int r = e >> 3, seg = (e & 7) << 2;
            cpa16(xd + r * 32 + seg, inB + (size_t)r * 128 + n * 32 + seg);
        }
        #pragma unroll
        for (int q = 0; q < 4; q++) {
            int e = q * 256 + t;
            int c = e >> 5, seg = (e & 31) << 2;
            cpa16(wd + c * 132 + seg, WT + (n * 32 + c) * 128 + seg);
        }
        CP_COMMIT();
    };

    u64 acc[8][4] = {};
    issue(0);
    int tr_r = t >> 1, tr_c0 = (t & 1) << 4;
    for (int i = 0; i < 4; i++) {
        CP_WAIT0();
        __syncthreads();
        if (i + 1 < 4) issue(i + 1);
        // transform: BN+ReLU + transpose stX[i&1] -> Xc ([c][row], 132 stride)
        {
            const float* src = stX + (i & 1) * 4096 + tr_r * 32 + tr_c0;
            int k0 = i * 32 + tr_c0;
            #pragma unroll
            for (int j = 0; j < 16; j += 4) {
                float4 v = *(const float4*)(src + j);
                Xc[(tr_c0 + j + 0) * 132 + tr_r] = fmaxf(fmaf(sa[k0+j+0], v.x, sb[k0+j+0]), 0.f);
                Xc[(tr_c0 + j + 1) * 132 + tr_r] = fmaxf(fmaf(sa[k0+j+1], v.y, sb[k0+j+1]), 0.f);
                Xc[(tr_c0 + j + 2) * 132 + tr_r] = fmaxf(fmaf(sa[k0+j+2], v.z, sb[k0+j+2]), 0.f);
                Xc[(tr_c0 + j + 3) * 132 + tr_r] = fmaxf(fmaf(sa[k0+j+3], v.w, sb[k0+j+3]), 0.f);
            }
        }
        __syncthreads();
        const float* Wb = Ws + (i & 1) * 4224;
        #pragma unroll 8
        for (int kk = 0; kk < 32; kk++) {
            ulonglong2 b01 = *(const ulonglong2*)(Wb + kk * 132 + tx * 8);
            ulonglong2 b23 = *(const ulonglong2*)(Wb + kk * 132 + tx * 8 + 4);
            u64 bv[4] = { b01.x, b01.y, b23.x, b23.y };
            float4 a0 = *(const float4*)(Xc + kk * 132 + ty * 8);
            float4 a1 = *(const float4*)(Xc + kk * 132 + ty * 8 + 4);
            float av[8] = { a0.x, a0.y, a0.z, a0.w, a1.x, a1.y, a1.z, a1.w };
            #pragma unroll
            for (int r = 0; r < 8; r++) {
                u64 ad = dup2(av[r]);
                #pragma unroll
                for (int c2 = 0; c2 < 4; c2++) ffma2(acc[r][c2], ad, bv[c2]);
            }
        }
    }

    float cs[8] = {}, cq[8] = {};
    #pragma unroll
    for (int r = 0; r < 8; r++) {
        float v[8];
        float2 p0 = up2(acc[r][0]), p1 = up2(acc[r][1]);
        float2 p2 = up2(acc[r][2]), p3 = up2(acc[r][3]);
        v[0]=p0.x; v[1]=p0.y; v[2]=p1.x; v[3]=p1.y;
        v[4]=p2.x; v[5]=p2.y; v[6]=p3.x; v[7]=p3.y;
        #pragma unroll
        for (int c = 0; c < 8; c++) { cs[c] += v[c]; cq[c] += v[c]*v[c]; }
        float* dst = outb + (rowBase + ty * 8 + r) * 128 + tx * 8;
        *(float4*)(dst)     = make_float4(v[0], v[1], v[2], v[3]);
        *(float4*)(dst + 4) = make_float4(v[4], v[5], v[6], v[7]);
    }
    #pragma unroll
    for (int c = 0; c < 8; c++) {
        atomicAdd(&bsum[tx * 8 + c], cs[c]);
        atomicAdd(&bsq [tx * 8 + c], cq[c]);
    }
    __syncthreads();
    if (t < 128) {
        atomicAdd(&d_stats[stageOut][0][t], bsum[t]);
        atomicAdd(&d_stats[stageOut][1][t], bsq[t]);
    }
}

// ---------------- max pools + output writes ----------------
__global__ void k_maxlocal(float* __restrict__ outF) {
    int bs = blockIdx.x;
    int o  = threadIdx.x;
    float a = d_ab[2][0][o], bb = d_ab[2][1][o];
    const float* base = d_zlA + (size_t)bs * NSk * 128 + o;
    float m = 0.f;
    #pragma unroll 4
    for (int k = 0; k < NSk; k++) m = fmaxf(m, fmaf(a, base[k * 128], bb));
    int b = bs >> 9, s = bs & 511;
    outF[((size_t)b * 256 + o) * 512 + s] = m;
}

__global__ void k_gmax1() {
    int b = blockIdx.y, sl = blockIdx.x, o = threadIdx.x;
    float a = d_ab[5][0][o], bb = d_ab[5][1][o];
    const float* base = d_zgA + ((size_t)b * Np + sl * 128) * 128 + o;
    float m = 0.f;
    #pragma unroll 4
    for (int k = 0; k < 128; k++) m = fmaxf(m, fmaf(a, base[k * 128], bb));
    d_gpart[(b * 32 + sl) * 128 + o] = m;
}

__global__ void k_gmax2(float* __restrict__ outF) {
    __shared__ float smx[128];
    int b = blockIdx.x, t = threadIdx.x;
    if (t < 128) {
        float m = 0.f;
        for (int sl = 0; sl < 32; sl++) m = fmaxf(m, d_gpart[(b * 32 + sl) * 128 + t]);
        smx[t] = m;
    }
    __syncthreads();
    for (int i = t; i < 128 * 512; i += 256) {
        int o = i >> 9, s = i & 511;
        outF[((size_t)b * 256 + 128 + o) * 512 + s] = smx[o];
    }
}

// ---------------- launch ----------------
extern "C" void kernel_launch(void* const* d_in, const int* in_sizes, int n_in,
                              void* d_out, int out_size) {
    (void)in_sizes; (void)n_in; (void)out_size;
    const float* xyz  = (const float*)d_in[0];
    const float* feat = (const float*)d_in[1];
    const int*   inds = (const int*)  d_in[2];
    const float* w10  = (const float*)d_in[3];
    const float* g10  = (const float*)d_in[4];
    const float* be10 = (const float*)d_in[5];
    const float* w11  = (const float*)d_in[6];
    const float* g11  = (const float*)d_in[7];
    const float* be11 = (const float*)d_in[8];
    const float* w12  = (const float*)d_in[9];
    const float* g12  = (const float*)d_in[10];
    const float* be12 = (const float*)d_in[11];
    const float* w20  = (const float*)d_in[12];
    const float* g20  = (const float*)d_in[13];
    const float* be20 = (const float*)d_in[14];
    const float* w21  = (const float*)d_in[15];
    const float* g21  = (const float*)d_in[16];
    const float* be21 = (const float*)d_in[17];
    const float* w22  = (const float*)d_in[18];
    const float* g22  = (const float*)d_in[19];
    const float* be22 = (const float*)d_in[20];

    float* out      = (float*)d_out;
    float* out_xyz  = out;                       // (B,S,3)
    float* out_feat = out + (size_t)Bq * Sq * 3; // (B,256,S)

    const float invL = 1.0f / (float)NROWS_L;
    const float invG = 1.0f / (float)NROWS_G;

    const int SMEM_L0 = 2 * 4224 * 2 * 4;                // 67584
    const int SMEM_GM = (2 * 4096 + 4224 + 2 * 4224) * 4; // 83456
    static int attr_done = 0;
    if (!attr_done) {
        cudaFuncSetAttribute(k_l0dense, cudaFuncAttributeMaxDynamicSharedMemorySize, SMEM_L0);
        cudaFuncSetAttribute(k_gemm128, cudaFuncAttributeMaxDynamicSharedMemorySize, SMEM_GM);
        attr_done = 1;
    }

    k_zero_stats<<<1, 128>>>();
    k_prep<<<256, 256>>>(w10, w20);
    k_prep2<<<256, 256>>>(w11, w12, w21, w22);
    k_ballquery<<<dim3(Sq / 8, Bq), 256>>>(xyz, inds, out_xyz);

    // layer 0: dense feature GEMM (F0 + global z0 with fused stage3 stats)
    k_l0dense<<<dim3(256, 2), 256, SMEM_L0>>>(feat, xyz);
    k_finalize<<<1, 128>>>(3, invG, g20, be20);

    // local assemble (fused stage0 stats)
    k_assemble<<<2048, 128>>>(xyz, out_xyz);
    k_finalize<<<1, 128>>>(0, invL, g10, be10);

    // local layers 1 & 2 (fused stats); wl: 0=w11 1=w12 2=w21 3=w22
    k_gemm128<<<NROWS_L / 128, 256, SMEM_GM>>>(0, 1, 0, 0, 1);
    k_finalize<<<1, 128>>>(1, invL, g11, be11);
    k_gemm128<<<NROWS_L / 128, 256, SMEM_GM>>>(1, 0, 1, 1, 2);
    k_finalize<<<1, 128>>>(2, invL, g12, be12);

    k_maxlocal<<<Bq * Sq, 128>>>(out_feat);

    // global layers 1 & 2 (fused stats)
    k_gemm128<<<NROWS_G / 128, 256, SMEM_GM>>>(2, 3, 2, 3, 4);
    k_finalize<<<1, 128>>>(4, invG, g21, be21);
    k_gemm128<<<NROWS_G / 128, 256, SMEM_GM>>>(3, 2, 3, 4, 5);
    k_finalize<<<1, 128>>>(5, invG, g22, be22);

    k_gmax1<<<dim3(32, Bq), 128>>>();
    k_gmax2<<<Bq, 256>>>(out_feat);
}

// round 15
// speedup vs baseline: 1.8189x; 1.0007x over previous
#include <cuda_runtime.h>

// Problem constants
#define Bq   8
#define Np   4096
#define Cc   256
#define Sq   512
#define NSk  64
#define NROWS_L (Bq*Sq*NSk)   /* 262144 */
#define NROWS_G (Bq*Np)       /* 32768  */

typedef unsigned long long u64;

// ---------------- f32x2 / async helpers ----------------
__device__ __forceinline__ void ffma2(u64& d, u64 a, u64 b) {
    asm("fma.rn.f32x2 %0, %1, %2, %0;" : "+l"(d) : "l"(a), "l"(b));
}
__device__ __forceinline__ u64 dup2(float x) {
    u64 r; unsigned xi = __float_as_uint(x);
    asm("mov.b64 %0, {%1, %1};" : "=l"(r) : "r"(xi));
    return r;
}
__device__ __forceinline__ float2 up2(u64 v) {
    float2 f;
    asm("mov.b64 {%0, %1}, %2;" : "=f"(f.x), "=f"(f.y) : "l"(v));
    return f;
}
__device__ __forceinline__ void cpa16(float* dst, const float* src) {
    unsigned d = (unsigned)__cvta_generic_to_shared(dst);
    asm volatile("cp.async.cg.shared.global [%0], [%1], 16;" :: "r"(d), "l"(src));
}
#define CP_COMMIT() asm volatile("cp.async.commit_group;")
#define CP_WAIT0()  asm volatile("cp.async.wait_group 0;")

// ---------------- device scratch (static, allocation-free) ----------------
__device__ int   d_idx[NROWS_L];
__device__ float d_WcT[256*256];                    // [c][o]  (o<128: w10 feat part, else w20)
__device__ float d_WTl[4*128*128];                  // transposed w11,w12,w21,w22  [l][c][o]
__device__ float d_Wx1[128*3];
__device__ float d_Wx2[128*3];
__device__ float d_F0 [(size_t)NROWS_G*128];
__device__ float d_zgA[(size_t)NROWS_G*128];
__device__ float d_zgB[(size_t)NROWS_G*128];
__device__ float d_zlA[(size_t)NROWS_L*128];
__device__ float d_zlB[(size_t)NROWS_L*128];
__device__ float d_stats[6][2][128];
__device__ float d_ab[6][2][128];
__device__ float d_gpart[Bq*32*128];

// device-side buffer resolution (NEVER pass __device__ symbols from host; R5 bug)
__device__ __forceinline__ float* bufptr(int w) {
    switch (w) {
        case 0:  return d_zlA;
        case 1:  return d_zlB;
        case 2:  return d_zgA;
        default: return d_zgB;
    }
}

// ---------------- tiny helpers ----------------
__global__ void k_zero_stats() {
    int i = threadIdx.x;
    if (i < 128)
        for (int s = 0; s < 6; s++)
            for (int h = 0; h < 2; h++)
                d_stats[s][h][i] = 0.f;
}

__global__ void k_prep(const float* __restrict__ w10, const float* __restrict__ w20) {
    int i = blockIdx.x * blockDim.x + threadIdx.x;   // 0..65535
    if (i < 256 * 256) {
        int c = i >> 8, o = i & 255;                 // WcT[c][o]
        d_WcT[i] = (o < 128) ? w10[o * 259 + 3 + c] : w20[(o - 128) * 259 + 3 + c];
    }
    if (i < 128 * 3) {
        int o = i / 3, dd = i % 3;
        d_Wx1[i] = w10[o * 259 + dd];
        d_Wx2[i] = w20[o * 259 + dd];
    }
}

__global__ void k_prep2(const float* __restrict__ w11, const float* __restrict__ w12,
                        const float* __restrict__ w21, const float* __restrict__ w22) {
    int i = blockIdx.x * blockDim.x + threadIdx.x;   // 0..65535
    int l = i >> 14, rem = i & 16383;
    int c = rem >> 7, o = rem & 127;
    const float* w = (l == 0) ? w11 : (l == 1) ? w12 : (l == 2) ? w21 : w22;
    d_WTl[i] = w[o * 128 + c];
}

// ---------------- ball query + new_xyz ----------------
__global__ void k_ballquery(const float* __restrict__ xyz,
                            const int*   __restrict__ inds,
                            float*       __restrict__ out_xyz) {
    __shared__ float sx[Np], sy[Np], sz[Np];
    int b = blockIdx.y;
    int t = threadIdx.x;
    const float* xb = xyz + (size_t)b * Np * 3;
    for (int i = t; i < Np; i += 256) {
        sx[i] = xb[i * 3 + 0];
        sy[i] = xb[i * 3 + 1];
        sz[i] = xb[i * 3 + 2];
    }
    __syncthreads();

    int w = t >> 5, lane = t & 31;
    int s = blockIdx.x * 8 + w;
    int q = inds[b * Sq + s];
    float qx = sx[q], qy = sy[q], qz = sz[q];
    if (lane == 0) out_xyz[(b * Sq + s) * 3 + 0] = qx;
    if (lane == 1) out_xyz[(b * Sq + s) * 3 + 1] = qy;
    if (lane == 2) out_xyz[(b * Sq + s) * 3 + 2] = qz;

    int* dst = d_idx + ((b * Sq + s) << 6);
    const float R2 = (float)(0.3 * 0.3);
    int count = 0, first = 0;
    for (int base = 0; base < Np; base += 32) {
        int j = base + lane;
        float dx = __fsub_rn(qx, sx[j]);
        float dy = __fsub_rn(qy, sy[j]);
        float dz = __fsub_rn(qz, sz[j]);
        float d2 = __fadd_rn(__fadd_rn(__fmul_rn(dx, dx), __fmul_rn(dy, dy)),
                             __fmul_rn(dz, dz));
        bool p = d2 < R2;
        unsigned m = __ballot_sync(0xffffffffu, p);
        if (count == 0 && m) first = base + __ffs(m) - 1;
        int pos = count + __popc(m & ((1u << lane) - 1u));
        if (p && pos < NSk) dst[pos] = j;
        count += __popc(m);
        if (count >= NSk) break;
    }
    for (int i = count + lane; i < NSk; i += 32) dst[i] = first;
}

// ---------------- dense layer0 GEMM (FFMA2 + cp.async double buffer) ----------
// grid (256, 2), block 256. K=256 in 8 chunks of 32. X already [c][j] in gmem.
// dyn smem: Xc[2][32*132] | Ws[2][32*132]  = 67584 B
__global__ __launch_bounds__(256, 2) void k_l0dense(const float* __restrict__ feat,
                                                    const float* __restrict__ xyz) {
    extern __shared__ float sm[];
    float* Xc = sm;                 // 2 * 4224
    float* Ws = sm + 2 * 4224;      // 2 * 4224
    __shared__ float bsum[128], bsq[128];
    int t = threadIdx.x;
    int oB = blockIdx.y;
    int rowBase = blockIdx.x * 128;          // global row = b*Np + j
    int b  = rowBase >> 12;
    int jb = rowBase & (Np - 1);
    if (t < 128) { bsum[t] = 0.f; bsq[t] = 0.f; }

    int ty = t >> 4, tx = t & 15;
    const float* fb = feat + (size_t)b * Cc * Np + jb;
    const float* Wg = d_WcT + oB * 128;      // row c: [c*256 + oB*128 .. +128)

    // chunk issue: 4 X copies + 4 W copies per thread
    auto issue = [&](int n) {
        float* xd = Xc + (n & 1) * 4224;
        float* wd = Ws + (n & 1) * 4224;
        #pragma unroll
        for (int q = 0; q < 4; q++) {
            int e = q * 256 + t;
            int c = e >> 5, seg = (e & 31) << 2;
            cpa16(xd + c * 132 + seg, fb + (size_t)(n * 32 + c) * Np + seg);
        }
        #pragma unroll
        for (int q = 0; q < 4; q++) {
            int e = q * 256 + t;
            int c = e >> 5, seg = (e & 31) << 2;
            cpa16(wd + c * 132 + seg, Wg + (n * 32 + c) * 256 + seg);
        }
        CP_COMMIT();
    };

    u64 acc[8][4] = {};
    issue(0);
    for (int i = 0; i < 8; i++) {
        CP_WAIT0();
        __syncthreads();
        if (i + 1 < 8) issue(i + 1);
        const float* Xb = Xc + (i & 1) * 4224;
        const float* Wb = Ws + (i & 1) * 4224;
        #pragma unroll 8
        for (int kk = 0; kk < 32; kk++) {
            ulonglong2 b01 = *(const ulonglong2*)(Wb + kk * 132 + tx * 8);
            ulonglong2 b23 = *(const ulonglong2*)(Wb + kk * 132 + tx * 8 + 4);
            u64 bv[4] = { b01.x, b01.y, b23.x, b23.y };
            float4 a0 = *(const float4*)(Xb + kk * 132 + ty * 8);
            float4 a1 = *(const float4*)(Xb + kk * 132 + ty * 8 + 4);
            float av[8] = { a0.x, a0.y, a0.z, a0.w, a1.x, a1.y, a1.z, a1.w };
            #pragma unroll
            for (int r = 0; r < 8; r++) {
                u64 ad = dup2(av[r]);
                #pragma unroll
                for (int c2 = 0; c2 < 4; c2++) ffma2(acc[r][c2], ad, bv[c2]);
            }
        }
        __syncthreads();
    }

    if (oB == 0) {
        #pragma unroll
        for (int r = 0; r < 8; r++) {
            float2 p0 = up2(acc[r][0]), p1 = up2(acc[r][1]);
            float2 p2 = up2(acc[r][2]), p3 = up2(acc[r][3]);
            float* dst = d_F0 + ((size_t)(rowBase + ty * 8 + r)) * 128 + tx * 8;
            *(float4*)(dst)     = make_float4(p0.x, p0.y, p1.x, p1.y);
            *(float4*)(dst + 4) = make_float4(p2.x, p2.y, p3.x, p3.y);
        }
    } else {
        float wx[8][3];
        #pragma unroll
        for (int c = 0; c < 8; c++) {
            int o = tx * 8 + c;
            wx[c][0] = d_Wx2[o * 3 + 0];
            wx[c][1] = d_Wx2[o * 3 + 1];
            wx[c][2] = d_Wx2[o * 3 + 2];
        }
        float cs[8] = {}, cq[8] = {};
        #pragma unroll
        for (int r = 0; r < 8; r++) {
            int row = rowBase + ty * 8 + r;
            const float* px = xyz + (size_t)row * 3;
            float x0 = px[0], x1 = px[1], x2 = px[2];
            float v[8];
            float2 p0 = up2(acc[r][0]), p1 = up2(acc[r][1]);
            float2 p2 = up2(acc[r][2]), p3 = up2(acc[r][3]);
            v[0]=p0.x; v[1]=p0.y; v[2]=p1.x; v[3]=p1.y;
            v[4]=p2.x; v[5]=p2.y; v[6]=p3.x; v[7]=p3.y;
            #pragma unroll
            for (int c = 0; c < 8; c++) {
                v[c] += wx[c][0]*x0 + wx[c][1]*x1 + wx[c][2]*x2;
                cs[c] += v[c]; cq[c] += v[c]*v[c];
            }
            float* dst = d_zgA + (size_t)row * 128 + tx * 8;
            *(float4*)(dst)     = make_float4(v[0], v[1], v[2], v[3]);
            *(float4*)(dst + 4) = make_float4(v[4], v[5], v[6], v[7]);
        }
        #pragma unroll
        for (int c = 0; c < 8; c++) {
            atomicAdd(&bsum[tx * 8 + c], cs[c]);
            atomicAdd(&bsq [tx * 8 + c], cq[c]);
        }
        __syncthreads();
        if (t < 128) {
            atomicAdd(&d_stats[3][0][t], bsum[t]);
            atomicAdd(&d_stats[3][1][t], bsq[t]);
        }
    }
}

// ---------------- local layer0 assemble + fused stage0 stats ----------------
__global__ void k_assemble(const float* __restrict__ xyz,
                           const float* __restrict__ nxyz) {
    __shared__ float sgx[128], sgy[128], sgz[128];
    __shared__ int   sj[128];
    int o = threadIdx.x;
    int row0 = blockIdx.x * 128;
    {
        int row = row0 + o;
        int b = row >> 15;
        int s = (row >> 6) & 511;
        int j = d_idx[row];
        const float* nx = nxyz + ((size_t)(b * Sq + s)) * 3;
        const float* px = xyz  + ((size_t)(b * Np + j)) * 3;
        sgx[o] = __fmul_rn(__fsub_rn(px[0], nx[0]), (1.0f/0.3f));
        sgy[o] = __fmul_rn(__fsub_rn(px[1], nx[1]), (1.0f/0.3f));
        sgz[o] = __fmul_rn(__fsub_rn(px[2], nx[2]), (1.0f/0.3f));
        sj[o]  = (b * Np) + j;
    }
    __syncthreads();
    float w0 = d_Wx1[o * 3 + 0], w1 = d_Wx1[o * 3 + 1], w2 = d_Wx1[o * 3 + 2];
    float s1 = 0.f, s2 = 0.f;
    #pragma unroll 4
    for (int rr = 0; rr < 128; rr++) {
        float v = d_F0[(size_t)sj[rr] * 128 + o]
                + w0 * sgx[rr] + w1 * sgy[rr] + w2 * sgz[rr];
        d_zlA[(size_t)(row0 + rr) * 128 + o] = v;
        s1 += v; s2 += v * v;
    }
    atomicAdd(&d_stats[0][0][o], s1);
    atomicAdd(&d_stats[0][1][o], s2);
}

__global__ void k_finalize(int stage, float invCnt,
                           const float* __restrict__ g,
                           const float* __restrict__ be) {
    int o = threadIdx.x;
    float mu  = d_stats[stage][0][o] * invCnt;
    float var = d_stats[stage][1][o] * invCnt - mu * mu;
    float a = g[o] / sqrtf(var + 1e-5f);
    d_ab[stage][0][o] = a;
    d_ab[stage][1][o] = be[o] - mu * a;
}

// ---------------- 128x128 layer GEMM (FFMA2 + cp.async + transform) --------
// dyn smem: stX[2][128*32] | Xc[32*132] | Ws[2][32*132]  = 83456 B
__global__ __launch_bounds__(256, 2) void k_gemm128(int inid, int outid, int wl,
                                                    int stageIn, int stageOut) {
    extern __shared__ float sm[];
    float* stX = sm;                      // 2 * 4096
    float* Xc  = sm + 8192;               // 4224
    float* Ws  = sm + 8192 + 4224;        // 2 * 4224
    __shared__ float sa[128], sb[128];
    __shared__ float bsum[128], bsq[128];
    const float* __restrict__ in = bufptr(inid);
    float* __restrict__ outb     = bufptr(outid);
    const float* WT = d_WTl + wl * 16384;
    int t = threadIdx.x;
    if (t < 128) {
        sa[t] = d_ab[stageIn][0][t];
        sb[t] = d_ab[stageIn][1][t];
        bsum[t] = 0.f; bsq[t] = 0.f;
    }
    size_t rowBase = (size_t)blockIdx.x * 128;
    const float* inB = in + rowBase * 128;
    int ty = t >> 4, tx = t & 15;

    auto issue = [&](int n) {
        float* xd = stX + (n & 1) * 4096;
        float* wd = Ws  + (n & 1) * 4224;
        #pragma unroll
        for (int q = 0; q < 4; q++) {
            int e = q * 256 + t;
            int r = e >> 3, seg = (e & 7) << 2;
            cpa16(xd + r * 32 + seg, inB + (size_t)r * 128 + n * 32 + seg);
        }
        #pragma unroll
        for (int q = 0; q < 4; q++) {
            int e = q * 256 + t;
            int c = e >> 5, seg = (e & 31) << 2;
            cpa16(wd + c * 132 + seg, WT + (n * 32 + c) * 128 + seg);
        }
        CP_COMMIT();
    };

    u64 acc[8][4] = {};
    issue(0);
    int tr_r = t >> 1, tr_c0 = (t & 1) << 4;
    for (int i = 0; i < 4; i++) {
        CP_WAIT0();
        __syncthreads();
        if (i + 1 < 4) issue(i + 1);
        // transform: BN+ReLU + transpose stX[i&1] -> Xc ([c][row], 132 stride)
        {
            const float* src = stX + (i & 1) * 4096 + tr_r * 32 + tr_c0;
            int k0 = i * 32 + tr_c0;
            #pragma unroll
            for (int j = 0; j < 16; j += 4) {
                float4 v = *(const float4*)(src + j);
                Xc[(tr_c0 + j + 0) * 132 + tr_r] = fmaxf(fmaf(sa[k0+j+0], v.x, sb[k0+j+0]), 0.f);
                Xc[(tr_c0 + j + 1) * 132 + tr_r] = fmaxf(fmaf(sa[k0+j+1], v.y, sb[k0+j+1]), 0.f);
                Xc[(tr_c0 + j + 2) * 132 + tr_r] = fmaxf(fmaf(sa[k0+j+2], v.z, sb[k0+j+2]), 0.f);
                Xc[(tr_c0 + j + 3) * 132 + tr_r] = fmaxf(fmaf(sa[k0+j+3], v.w, sb[k0+j+3]), 0.f);
            }
        }
        __syncthreads();
        const float* Wb = Ws + (i & 1) * 4224;
        #pragma unroll 8
        for (int kk = 0; kk < 32; kk++) {
            ulonglong2 b01 = *(const ulonglong2*)(Wb + kk * 132 + tx * 8);
            ulonglong2 b23 = *(const ulonglong2*)(Wb + kk * 132 + tx * 8 + 4);
            u64 bv[4] = { b01.x, b01.y, b23.x, b23.y };
            float4 a0 = *(const float4*)(Xc + kk * 132 + ty * 8);
            float4 a1 = *(const float4*)(Xc + kk * 132 + ty * 8 + 4);
            float av[8] = { a0.x, a0.y, a0.z, a0.w, a1.x, a1.y, a1.z, a1.w };
            #pragma unroll
            for (int r = 0; r < 8; r++) {
                u64 ad = dup2(av[r]);
                #pragma unroll
                for (int c2 = 0; c2 < 4; c2++) ffma2(acc[r][c2], ad, bv[c2]);
            }
        }
    }

    float cs[8] = {}, cq[8] = {};
    #pragma unroll
    for (int r = 0; r < 8; r++) {
        float v[8];
        float2 p0 = up2(acc[r][0]), p1 = up2(acc[r][1]);
        float2 p2 = up2(acc[r][2]), p3 = up2(acc[r][3]);
        v[0]=p0.x; v[1]=p0.y; v[2]=p1.x; v[3]=p1.y;
        v[4]=p2.x; v[5]=p2.y; v[6]=p3.x; v[7]=p3.y;
        #pragma unroll
        for (int c = 0; c < 8; c++) { cs[c] += v[c]; cq[c] += v[c]*v[c]; }
        float* dst = outb + (rowBase + ty * 8 + r) * 128 + tx * 8;
        *(float4*)(dst)     = make_float4(v[0], v[1], v[2], v[3]);
        *(float4*)(dst + 4) = make_float4(v[4], v[5], v[6], v[7]);
    }
    #pragma unroll
    for (int c = 0; c < 8; c++) {
        atomicAdd(&bsum[tx * 8 + c], cs[c]);
        atomicAdd(&bsq [tx * 8 + c], cq[c]);
    }
    __syncthreads();
    if (t < 128) {
        atomicAdd(&d_stats[stageOut][0][t], bsum[t]);
        atomicAdd(&d_stats[stageOut][1][t], bsq[t]);
    }
}

// ---------------- max pools + output writes ----------------
__global__ void k_maxlocal(float* __restrict__ outF) {
    int bs = blockIdx.x;
    int o  = threadIdx.x;
    float a = d_ab[2][0][o], bb = d_ab[2][1][o];
    const float* base = d_zlA + (size_t)bs * NSk * 128 + o;
    float m = 0.f;
    #pragma unroll 4
    for (int k = 0; k < NSk; k++) m = fmaxf(m, fmaf(a, base[k * 128], bb));
    int b = bs >> 9, s = bs & 511;
    outF[((size_t)b * 256 + o) * 512 + s] = m;
}

__global__ void k_gmax1() {
    int b = blockIdx.y, sl = blockIdx.x, o = threadIdx.x;
    float a = d_ab[5][0][o], bb = d_ab[5][1][o];
    const float* base = d_zgA + ((size_t)b * Np + sl * 128) * 128 + o;
    float m = 0.f;
    #pragma unroll 4
    for (int k = 0; k < 128; k++) m = fmaxf(m, fmaf(a, base[k * 128], bb));
    d_gpart[(b * 32 + sl) * 128 + o] = m;
}

__global__ void k_gmax2(float* __restrict__ outF) {
    __shared__ float smx[128];
    int b = blockIdx.x, t = threadIdx.x;
    if (t < 128) {
        float m = 0.f;
        for (int sl = 0; sl < 32; sl++) m = fmaxf(m, d_gpart[(b * 32 + sl) * 128 + t]);
        smx[t] = m;
    }
    __syncthreads();
    for (int i = t; i < 128 * 512; i += 256) {
        int o = i >> 9, s = i & 511;
        outF[((size_t)b * 256 + 128 + o) * 512 + s] = smx[o];
    }
}

// ---------------- launch ----------------
extern "C" void kernel_launch(void* const* d_in, const int* in_sizes, int n_in,
                              void* d_out, int out_size) {
    (void)in_sizes; (void)n_in; (void)out_size;
    const float* xyz  = (const float*)d_in[0];
    const float* feat = (const float*)d_in[1];
    const int*   inds = (const int*)  d_in[2];
    const float* w10  = (const float*)d_in[3];
    const float* g10  = (const float*)d_in[4];
    const float* be10 = (const float*)d_in[5];
    const float* w11  = (const float*)d_in[6];
    const float* g11  = (const float*)d_in[7];
    const float* be11 = (const float*)d_in[8];
    const float* w12  = (const float*)d_in[9];
    const float* g12  = (const float*)d_in[10];
    const float* be12 = (const float*)d_in[11];
    const float* w20  = (const float*)d_in[12];
    const float* g20  = (const float*)d_in[13];
    const float* be20 = (const float*)d_in[14];
    const float* w21  = (const float*)d_in[15];
    const float* g21  = (const float*)d_in[16];
    const float* be21 = (const float*)d_in[17];
    const float* w22  = (const float*)d_in[18];
    const float* g22  = (const float*)d_in[19];
    const float* be22 = (const float*)d_in[20];

    float* out      = (float*)d_out;
    float* out_xyz  = out;                       // (B,S,3)
    float* out_feat = out + (size_t)Bq * Sq * 3; // (B,256,S)

    const float invL = 1.0f / (float)NROWS_L;
    const float invG = 1.0f / (float)NROWS_G;

    const int SMEM_L0 = 2 * 4224 * 2 * 4;                // 67584
    const int SMEM_GM = (2 * 4096 + 4224 + 2 * 4224) * 4; // 83456
    static int attr_done = 0;
    if (!attr_done) {
        cudaFuncSetAttribute(k_l0dense, cudaFuncAttributeMaxDynamicSharedMemorySize, SMEM_L0);
        cudaFuncSetAttribute(k_gemm128, cudaFuncAttributeMaxDynamicSharedMemorySize, SMEM_GM);
        attr_done = 1;
    }

    k_zero_stats<<<1, 128>>>();
    k_prep<<<256, 256>>>(w10, w20);
    k_prep2<<<256, 256>>>(w11, w12, w21, w22);
    k_ballquery<<<dim3(Sq / 8, Bq), 256>>>(xyz, inds, out_xyz);

    // layer 0: dense feature GEMM (F0 + global z0 with fused stage3 stats)
    k_l0dense<<<dim3(256, 2), 256, SMEM_L0>>>(feat, xyz);
    k_finalize<<<1, 128>>>(3, invG, g20, be20);

    // local assemble (fused stage0 stats)
    k_assemble<<<2048, 128>>>(xyz, out_xyz);
    k_finalize<<<1, 128>>>(0, invL, g10, be10);

    // local layers 1 & 2 (fused stats); wl: 0=w11 1=w12 2=w21 3=w22
    k_gemm128<<<NROWS_L / 128, 256, SMEM_GM>>>(0, 1, 0, 0, 1);
    k_finalize<<<1, 128>>>(1, invL, g11, be11);
    k_gemm128<<<NROWS_L / 128, 256, SMEM_GM>>>(1, 0, 1, 1, 2);
    k_finalize<<<1, 128>>>(2, invL, g12, be12);

    k_maxlocal<<<Bq * Sq, 128>>>(out_feat);

    // global layers 1 & 2 (fused stats)
    k_gemm128<<<NROWS_G / 128, 256, SMEM_GM>>>(2, 3, 2, 3, 4);
    k_finalize<<<1, 128>>>(4, invG, g21, be21);
    k_gemm128<<<NROWS_G / 128, 256, SMEM_GM>>>(3, 2, 3, 4, 5);
    k_finalize<<<1, 128>>>(5, invG, g22, be22);

    k_gmax1<<<dim3(32, Bq), 128>>>();
    k_gmax2<<<Bq, 256>>>(out_feat);
}